// round 9
// baseline (speedup 1.0000x reference)
#include <cuda_runtime.h>
#include <math.h>
#include <stdint.h>

#define EMBED   1024
#define NHEADS  16
#define HDIM    64
#define BATCH   2
#define QLEN    2048
#define CLEN    2048
#define MROWS   (BATCH * QLEN)   // 4096
#define KP      (EMBED / 2)      // 512 u32 pairs per row

__device__ __align__(16) uint32_t g_Xqh[MROWS * KP];
__device__ __align__(16) uint32_t g_Xch[MROWS * KP];
__device__ __align__(16) uint32_t g_Wh[4][KP * EMBED];
__device__ __align__(16) uint32_t g_Qh[MROWS * KP];
__device__ __align__(16) uint32_t g_Kh[MROWS * KP];
__device__ __align__(16) float    g_Vf[MROWS * EMBED];
__device__ __align__(16) uint32_t g_Ah[MROWS * KP];

__device__ __forceinline__ uint32_t f2h2(float lo, float hi) {
    uint32_t r;
    asm("cvt.rn.f16x2.f32 %0, %1, %2;" : "=r"(r) : "f"(hi), "f"(lo));
    return r;
}
__device__ __forceinline__ uint32_t smem_u32(const void* p) {
    return (uint32_t)__cvta_generic_to_shared(p);
}
__device__ __forceinline__ void cp16(uint32_t saddr, const void* g) {
    asm volatile("cp.async.cg.shared.global [%0], [%1], 16;" :: "r"(saddr), "l"(g));
}
#define CP_COMMIT() asm volatile("cp.async.commit_group;" ::: "memory")
#define CP_WAIT(n)  asm volatile("cp.async.wait_group %0;" :: "n"(n) : "memory")

#define MMA_F16(d, a, b)                                                   \
    asm volatile(                                                          \
        "mma.sync.aligned.m16n8k16.row.col.f32.f16.f16.f32 "               \
        "{%0,%1,%2,%3}, {%4,%5,%6,%7}, {%8,%9}, {%0,%1,%2,%3};"            \
        : "+f"(d[0]), "+f"(d[1]), "+f"(d[2]), "+f"(d[3])                   \
        : "r"(a[0]), "r"(a[1]), "r"(a[2]), "r"(a[3]), "r"(b[0]), "r"(b[1]))

// ---------------------------------------------------------------------------
// Prepass: pack fp32 -> fp16 pairs.
// ---------------------------------------------------------------------------
__global__ void __launch_bounds__(256) prepack_kernel(
    const float* __restrict__ q, const float* __restrict__ ctx,
    const float* __restrict__ Wq, const float* __restrict__ Wk,
    const float* __restrict__ Wv, const float* __restrict__ Wo)
{
    const int z = blockIdx.z;
    const int stride = gridDim.x * blockDim.x;
    int i0 = blockIdx.x * blockDim.x + threadIdx.x;

    if (z < 2) {
        const float* src = (z == 0) ? q : ctx;
        uint2* dst = (uint2*)((z == 0) ? g_Xqh : g_Xch);
        const int count = MROWS * KP / 2;
        for (int i = i0; i < count; i += stride) {
            float4 v = ((const float4*)src)[i];
            dst[i] = make_uint2(f2h2(v.x, v.y), f2h2(v.z, v.w));
        }
    } else {
        const float* W = (z == 2) ? Wq : (z == 3) ? Wk : (z == 4) ? Wv : Wo;
        uint4* dst = (uint4*)g_Wh[z - 2];
        const int count = KP * EMBED / 4;
        for (int i = i0; i < count; i += stride) {
            int kp = i >> 8;
            int n4 = (i & 255) * 4;
            float4 a = *(const float4*)&W[(size_t)(2 * kp) * EMBED + n4];
            float4 b = *(const float4*)&W[(size_t)(2 * kp + 1) * EMBED + n4];
            dst[i] = make_uint4(f2h2(a.x, b.x), f2h2(a.y, b.y),
                                f2h2(a.z, b.z), f2h2(a.w, b.w));
        }
    }
}

// ---------------------------------------------------------------------------
// fp16 GEMM + bias, 3-stage cp.async pipeline.
// CTA 128x128, BK=32 (2 mma k-steps/stage), 256 threads (8 warps, 2x4),
// warp tile 64x32 (mt=4, nt=4).
// ---------------------------------------------------------------------------
#define NSTG 3
#define PAH  20                 // A stage pitch (u32): 16 data + 4 pad
#define PBH  136                // B stage pitch (u32)
#define ASTG (128 * PAH)        // 2560 u32
#define BSTG (16 * PBH)         // 2176 u32
#define GSMEM ((NSTG * (ASTG + BSTG)) * 4)   // 56832 B

__device__ __forceinline__ void gemm_h_body(
    const uint32_t* __restrict__ A, const uint32_t* __restrict__ W,
    const float* __restrict__ bias, void* __restrict__ Cout,
    int outHalf, float oscale, int bx, int by)
{
    extern __shared__ uint32_t gsm[];
    uint32_t* As = gsm;                 // [NSTG][128][PAH]
    uint32_t* Bs = gsm + NSTG * ASTG;   // [NSTG][16][PBH]
    const uint32_t sAs = smem_u32(As);
    const uint32_t sBs = smem_u32(Bs);

    const int tid  = threadIdx.x;
    const int lane = tid & 31;
    const int warp = tid >> 5;             // 0..7
    const int g    = lane >> 2;
    const int tg   = lane & 3;
    const int wr   = (warp >> 2) * 64;     // 0,64
    const int wc   = (warp & 3) * 32;      // 0,32,64,96
    const int rowBase = by * 128;
    const int colBase = bx * 128;
    const int KT = 32;                     // 1024 / 32

    // cp.async chunk coords (2 chunks each for A and B per stage)
    const int c0 = 2 * tid, c1 = 2 * tid + 1;
    const int am0 = c0 >> 2, aq0 = (c0 & 3) * 4;
    const int am1 = c1 >> 2, aq1 = (c1 & 3) * 4;
    const int br0 = c0 >> 5, bn0 = (c0 & 31) * 4;
    const int br1 = c1 >> 5, bn1 = (c1 & 31) * 4;

    const uint32_t* A0 = A + (size_t)(rowBase + am0) * KP + aq0;
    const uint32_t* A1 = A + (size_t)(rowBase + am1) * KP + aq1;
    const uint32_t* W0 = W + (size_t)br0 * EMBED + colBase + bn0;
    const uint32_t* W1 = W + (size_t)br1 * EMBED + colBase + bn1;

    auto issue = [&](int stg, int kt) {
        uint32_t sa = sAs + (uint32_t)(stg * ASTG) * 4;
        uint32_t sb = sBs + (uint32_t)(stg * BSTG) * 4;
        cp16(sa + (am0 * PAH + aq0) * 4, A0 + kt * 16);
        cp16(sa + (am1 * PAH + aq1) * 4, A1 + kt * 16);
        cp16(sb + (br0 * PBH + bn0) * 4, W0 + (size_t)(kt * 16) * EMBED);
        cp16(sb + (br1 * PBH + bn1) * 4, W1 + (size_t)(kt * 16) * EMBED);
        CP_COMMIT();
    };

    float acc[4][4][4];
    #pragma unroll
    for (int mt = 0; mt < 4; mt++)
        #pragma unroll
        for (int nt = 0; nt < 4; nt++)
            #pragma unroll
            for (int e = 0; e < 4; e++) acc[mt][nt][e] = 0.f;

    issue(0, 0);
    issue(1, 1);

    for (int kt = 0; kt < KT; kt++) {
        const int stg = kt % NSTG;
        if (kt + 1 < KT) { CP_WAIT(1); } else { CP_WAIT(0); }
        __syncthreads();

        const uint32_t* Ac = As + stg * ASTG;
        const uint32_t* Bc = Bs + stg * BSTG;

        #pragma unroll
        for (int s = 0; s < 2; s++) {
            const int kb = 8 * s;
            uint32_t a[4][4];
            #pragma unroll
            for (int mt = 0; mt < 4; mt++) {
                int m = wr + mt * 16 + g;
                a[mt][0] = Ac[m * PAH + kb + tg];
                a[mt][1] = Ac[(m + 8) * PAH + kb + tg];
                a[mt][2] = Ac[m * PAH + kb + tg + 4];
                a[mt][3] = Ac[(m + 8) * PAH + kb + tg + 4];
            }
            #pragma unroll
            for (int nt = 0; nt < 4; nt++) {
                uint32_t b[2];
                int n = wc + nt * 8 + g;
                b[0] = Bc[(kb + tg) * PBH + n];
                b[1] = Bc[(kb + tg + 4) * PBH + n];
                #pragma unroll
                for (int mt = 0; mt < 4; mt++)
                    MMA_F16(acc[mt][nt], a[mt], b);
            }
        }
        if (kt + 2 < KT) issue((kt + 2) % NSTG, kt + 2);
    }

    if (outHalf) {
        uint32_t* C = (uint32_t*)Cout;
        #pragma unroll
        for (int mt = 0; mt < 4; mt++) {
            #pragma unroll
            for (int nt = 0; nt < 4; nt++) {
                int row  = rowBase + wr + mt * 16 + g;
                int col  = colBase + wc + nt * 8 + 2 * tg;
                int colp = col >> 1;
                float2 bv = *(const float2*)&bias[col];
                C[(size_t)row * KP + colp] =
                    f2h2((acc[mt][nt][0] + bv.x) * oscale,
                         (acc[mt][nt][1] + bv.y) * oscale);
                C[(size_t)(row + 8) * KP + colp] =
                    f2h2((acc[mt][nt][2] + bv.x) * oscale,
                         (acc[mt][nt][3] + bv.y) * oscale);
            }
        }
    } else {
        float* C = (float*)Cout;
        #pragma unroll
        for (int mt = 0; mt < 4; mt++) {
            #pragma unroll
            for (int nt = 0; nt < 4; nt++) {
                int row = rowBase + wr + mt * 16 + g;
                int col = colBase + wc + nt * 8 + 2 * tg;
                float2 bv = *(const float2*)&bias[col];
                float2 r0 = make_float2(acc[mt][nt][0] + bv.x, acc[mt][nt][1] + bv.y);
                float2 r1 = make_float2(acc[mt][nt][2] + bv.x, acc[mt][nt][3] + bv.y);
                *(float2*)&C[(size_t)row * EMBED + col]       = r0;
                *(float2*)&C[(size_t)(row + 8) * EMBED + col] = r1;
            }
        }
    }
}

__global__ void __launch_bounds__(256) gemm_qkv_kernel(
    const float* __restrict__ bq, const float* __restrict__ bk,
    const float* __restrict__ bv)
{
    const int z = blockIdx.z;
    if (z == 0)      gemm_h_body(g_Xqh, g_Wh[0], bq, g_Qh, 1, 0.125f, blockIdx.x, blockIdx.y);
    else if (z == 1) gemm_h_body(g_Xch, g_Wh[1], bk, g_Kh, 1, 1.0f,   blockIdx.x, blockIdx.y);
    else             gemm_h_body(g_Xch, g_Wh[2], bv, g_Vf, 0, 1.0f,   blockIdx.x, blockIdx.y);
}

__global__ void __launch_bounds__(256) gemm_o_kernel(
    const float* __restrict__ bo, float* __restrict__ out)
{
    gemm_h_body(g_Ah, g_Wh[3], bo, out, 0, 1.0f, blockIdx.x, blockIdx.y);
}

// ---------------------------------------------------------------------------
// Flash attention fp16, P in registers (unchanged from R8 best).
// ---------------------------------------------------------------------------
#define PKH 36
#define PVH 72
#define PPH 36
#define FSM_TOTAL ((2 * 64 * PKH + 2 * 32 * PVH + 128 * PPH) * 4)

__global__ void __launch_bounds__(128) flash_h_kernel()
{
    extern __shared__ uint32_t sm[];
    uint32_t* Ks = sm;
    uint32_t* Vs = sm + 2 * 64 * PKH;
    uint32_t* Qstage = sm + 2 * 64 * PKH + 2 * 32 * PVH;

    const int b  = blockIdx.z;
    const int h  = blockIdx.y;
    const int q0 = blockIdx.x * 128;
    const int tid  = threadIdx.x;
    const int lane = tid & 31;
    const int warp = tid >> 5;
    const int g    = lane >> 2;
    const int tg   = lane & 3;
    const int mrow = warp * 32;

    const uint32_t* Qb = g_Qh + (size_t)b * QLEN * KP + h * 32;
    const uint32_t* Kb = g_Kh + (size_t)b * CLEN * KP + h * 32;
    const float*    Vb = g_Vf + (size_t)b * CLEN * EMBED + h * HDIM;

    const int kvr = tid >> 3;
    const int dq  = (tid & 7) * 4;
    uint4 kpf[4];
    auto ldgK = [&](int kt) {
        #pragma unroll
        for (int i = 0; i < 4; i++)
            kpf[i] = *(const uint4*)&Kb[(size_t)(kt * 64 + kvr + 16 * i) * KP + dq];
    };
    auto stsK = [&](uint32_t* dst) {
        #pragma unroll
        for (int i = 0; i < 4; i++)
            *(uint4*)&dst[(kvr + 16 * i) * PKH + dq] = kpf[i];
    };

    const int va_ = tid >> 4;
    const int dcol = (tid & 15) * 4;
    float4 vpa[4], vpb[4];
    auto ldgV = [&](int kt) {
        #pragma unroll
        for (int i = 0; i < 4; i++) {
            int kv2 = kt * 64 + 2 * (va_ + 8 * i);
            vpa[i] = *(const float4*)&Vb[(size_t)kv2 * EMBED + dcol];
            vpb[i] = *(const float4*)&Vb[(size_t)(kv2 + 1) * EMBED + dcol];
        }
    };
    auto stsV = [&](uint32_t* dst) {
        #pragma unroll
        for (int i = 0; i < 4; i++) {
            uint4 u = make_uint4(f2h2(vpa[i].x, vpb[i].x), f2h2(vpa[i].y, vpb[i].y),
                                 f2h2(vpa[i].z, vpb[i].z), f2h2(vpa[i].w, vpb[i].w));
            *(uint4*)&dst[(va_ + 8 * i) * PVH + dcol] = u;
        }
    };

    #pragma unroll
    for (int i = 0; i < 8; i++) {
        int idx = tid + i * 128;
        int r = idx >> 3;
        int q4 = (idx & 7) * 4;
        uint4 v = *(const uint4*)&Qb[(size_t)(q0 + r) * KP + q4];
        *(uint4*)&Qstage[r * PPH + q4] = v;
    }
    ldgK(0);
    __syncthreads();

    uint32_t qf[2][4][4];
    #pragma unroll
    for (int mt = 0; mt < 2; mt++) {
        int m = mrow + mt * 16 + g;
        #pragma unroll
        for (int s = 0; s < 4; s++) {
            qf[mt][s][0] = Qstage[m * PPH + 8 * s + tg];
            qf[mt][s][1] = Qstage[(m + 8) * PPH + 8 * s + tg];
            qf[mt][s][2] = Qstage[m * PPH + 8 * s + tg + 4];
            qf[mt][s][3] = Qstage[(m + 8) * PPH + 8 * s + tg + 4];
        }
    }
    stsK(Ks);
    ldgV(0);
    stsV(Vs);
    __syncthreads();

    float m_[4], l_[4];
    #pragma unroll
    for (int i = 0; i < 4; i++) { m_[i] = -INFINITY; l_[i] = 0.f; }
    float o[2][8][4];
    #pragma unroll
    for (int mt = 0; mt < 2; mt++)
        #pragma unroll
        for (int nt = 0; nt < 8; nt++)
            #pragma unroll
            for (int e = 0; e < 4; e++) o[mt][nt][e] = 0.f;

    const int NT = CLEN / 64;
    for (int kt = 0; kt < NT; kt++) {
        const int buf = kt & 1;
        uint32_t* Kcur = Ks + buf * 64 * PKH;
        uint32_t* Vcur = Vs + buf * 32 * PVH;
        uint32_t* Knxt = Ks + (buf ^ 1) * 64 * PKH;
        uint32_t* Vnxt = Vs + (buf ^ 1) * 32 * PVH;

        if (kt + 1 < NT) ldgK(kt + 1);

        float sacc[2][8][4];
        #pragma unroll
        for (int mt = 0; mt < 2; mt++)
            #pragma unroll
            for (int nt = 0; nt < 8; nt++)
                #pragma unroll
                for (int e = 0; e < 4; e++) sacc[mt][nt][e] = 0.f;

        #pragma unroll
        for (int s = 0; s < 4; s++) {
            #pragma unroll
            for (int nt = 0; nt < 8; nt++) {
                uint32_t bf[2];
                bf[0] = Kcur[(nt * 8 + g) * PKH + 8 * s + tg];
                bf[1] = Kcur[(nt * 8 + g) * PKH + 8 * s + tg + 4];
                MMA_F16(sacc[0][nt], qf[0][s], bf);
                MMA_F16(sacc[1][nt], qf[1][s], bf);
            }
        }

        if (kt + 1 < NT) {
            stsK(Knxt);
            ldgV(kt + 1);
        }

        #pragma unroll
        for (int mt = 0; mt < 2; mt++) {
            float mx0 = -INFINITY, mx1 = -INFINITY;
            #pragma unroll
            for (int nt = 0; nt < 8; nt++) {
                mx0 = fmaxf(mx0, fmaxf(sacc[mt][nt][0], sacc[mt][nt][1]));
                mx1 = fmaxf(mx1, fmaxf(sacc[mt][nt][2], sacc[mt][nt][3]));
            }
            #pragma unroll
            for (int off = 1; off < 4; off <<= 1) {
                mx0 = fmaxf(mx0, __shfl_xor_sync(0xffffffffu, mx0, off));
                mx1 = fmaxf(mx1, __shfl_xor_sync(0xffffffffu, mx1, off));
            }
            float mn0 = fmaxf(m_[2 * mt],     mx0);
            float mn1 = fmaxf(m_[2 * mt + 1], mx1);
            float c0 = __expf(m_[2 * mt]     - mn0);
            float c1 = __expf(m_[2 * mt + 1] - mn1);

            float rs0 = 0.f, rs1 = 0.f;
            #pragma unroll
            for (int nt = 0; nt < 8; nt++) {
                sacc[mt][nt][0] = __expf(sacc[mt][nt][0] - mn0);
                sacc[mt][nt][1] = __expf(sacc[mt][nt][1] - mn0);
                sacc[mt][nt][2] = __expf(sacc[mt][nt][2] - mn1);
                sacc[mt][nt][3] = __expf(sacc[mt][nt][3] - mn1);
                rs0 += sacc[mt][nt][0] + sacc[mt][nt][1];
                rs1 += sacc[mt][nt][2] + sacc[mt][nt][3];
            }
            #pragma unroll
            for (int off = 1; off < 4; off <<= 1) {
                rs0 += __shfl_xor_sync(0xffffffffu, rs0, off);
                rs1 += __shfl_xor_sync(0xffffffffu, rs1, off);
            }
            l_[2 * mt]     = l_[2 * mt]     * c0 + rs0;
            l_[2 * mt + 1] = l_[2 * mt + 1] * c1 + rs1;
            m_[2 * mt]     = mn0;
            m_[2 * mt + 1] = mn1;
            #pragma unroll
            for (int nt = 0; nt < 8; nt++) {
                o[mt][nt][0] *= c0; o[mt][nt][1] *= c0;
                o[mt][nt][2] *= c1; o[mt][nt][3] *= c1;
            }
        }

        #pragma unroll
        for (int s = 0; s < 4; s++) {
            uint32_t af[2][4];
            #pragma unroll
            for (int mt = 0; mt < 2; mt++) {
                af[mt][0] = f2h2(sacc[mt][2 * s][0],     sacc[mt][2 * s][1]);
                af[mt][1] = f2h2(sacc[mt][2 * s][2],     sacc[mt][2 * s][3]);
                af[mt][2] = f2h2(sacc[mt][2 * s + 1][0], sacc[mt][2 * s + 1][1]);
                af[mt][3] = f2h2(sacc[mt][2 * s + 1][2], sacc[mt][2 * s + 1][3]);
            }
            #pragma unroll
            for (int nt = 0; nt < 8; nt++) {
                uint32_t bf[2];
                bf[0] = Vcur[(8 * s + tg) * PVH + nt * 8 + g];
                bf[1] = Vcur[(8 * s + tg + 4) * PVH + nt * 8 + g];
                MMA_F16(o[0][nt], af[0], bf);
                MMA_F16(o[1][nt], af[1], bf);
            }
        }

        if (kt + 1 < NT) stsV(Vnxt);
        __syncthreads();
    }

    uint32_t* Ab = g_Ah + (size_t)b * QLEN * KP + h * 32;
    #pragma unroll
    for (int mt = 0; mt < 2; mt++) {
        float i0 = 1.f / l_[2 * mt];
        float i1 = 1.f / l_[2 * mt + 1];
        int r0 = q0 + mrow + mt * 16 + g;
        #pragma unroll
        for (int nt = 0; nt < 8; nt++) {
            int colp = nt * 4 + tg;
            Ab[(size_t)r0 * KP + colp]       = f2h2(o[mt][nt][0] * i0, o[mt][nt][1] * i0);
            Ab[(size_t)(r0 + 8) * KP + colp] = f2h2(o[mt][nt][2] * i1, o[mt][nt][3] * i1);
        }
    }
}

// ---------------------------------------------------------------------------
extern "C" void kernel_launch(void* const* d_in, const int* in_sizes, int n_in,
                              void* d_out, int out_size)
{
    const float* query   = (const float*)d_in[0];
    const float* context = (const float*)d_in[1];
    const float* Wq = (const float*)d_in[2];
    const float* bq = (const float*)d_in[3];
    const float* Wk = (const float*)d_in[4];
    const float* bk = (const float*)d_in[5];
    const float* Wv = (const float*)d_in[6];
    const float* bv = (const float*)d_in[7];
    const float* Wo = (const float*)d_in[8];
    const float* bo = (const float*)d_in[9];
    float* out = (float*)d_out;

    prepack_kernel<<<dim3(256, 1, 6), 256>>>(query, context, Wq, Wk, Wv, Wo);

    cudaFuncSetAttribute(gemm_qkv_kernel,
                         cudaFuncAttributeMaxDynamicSharedMemorySize, GSMEM);
    cudaFuncSetAttribute(gemm_o_kernel,
                         cudaFuncAttributeMaxDynamicSharedMemorySize, GSMEM);

    dim3 gQKV(EMBED / 128, MROWS / 128, 3);   // (8, 32, 3)
    gemm_qkv_kernel<<<gQKV, 256, GSMEM>>>(bq, bk, bv);

    cudaFuncSetAttribute(flash_h_kernel,
                         cudaFuncAttributeMaxDynamicSharedMemorySize, FSM_TOTAL);
    flash_h_kernel<<<dim3(QLEN / 128, NHEADS, BATCH), 128, FSM_TOTAL>>>();

    dim3 gGemm(EMBED / 128, MROWS / 128);     // (8, 32)
    gemm_o_kernel<<<gGemm, 256, GSMEM>>>(bo, out);
}

// round 10
// speedup vs baseline: 1.0294x; 1.0294x over previous
#include <cuda_runtime.h>
#include <math.h>
#include <stdint.h>

#define EMBED   1024
#define NHEADS  16
#define HDIM    64
#define BATCH   2
#define QLEN    2048
#define CLEN    2048
#define MROWS   (BATCH * QLEN)   // 4096
#define KP      (EMBED / 2)      // 512 u32 pairs per row

__device__ __align__(16) uint32_t g_Xqh[MROWS * KP];
__device__ __align__(16) uint32_t g_Xch[MROWS * KP];
__device__ __align__(16) uint32_t g_Wt[4][EMBED * KP];   // transposed: [n][kp]
__device__ __align__(16) uint32_t g_Qh[MROWS * KP];
__device__ __align__(16) uint32_t g_Kh[MROWS * KP];
__device__ __align__(16) float    g_Vf[MROWS * EMBED];
__device__ __align__(16) uint32_t g_Ah[MROWS * KP];

__device__ __forceinline__ uint32_t f2h2(float lo, float hi) {
    uint32_t r;
    asm("cvt.rn.f16x2.f32 %0, %1, %2;" : "=r"(r) : "f"(hi), "f"(lo));
    return r;
}
__device__ __forceinline__ uint32_t smem_u32(const void* p) {
    return (uint32_t)__cvta_generic_to_shared(p);
}
__device__ __forceinline__ void cp16(uint32_t saddr, const void* g) {
    asm volatile("cp.async.cg.shared.global [%0], [%1], 16;" :: "r"(saddr), "l"(g));
}
#define CP_COMMIT() asm volatile("cp.async.commit_group;" ::: "memory")
#define CP_WAIT(n)  asm volatile("cp.async.wait_group %0;" :: "n"(n) : "memory")

#define LDSM4(r0, r1, r2, r3, a)                                           \
    asm volatile("ldmatrix.sync.aligned.m8n8.x4.shared.b16 {%0,%1,%2,%3}, [%4];" \
        : "=r"(r0), "=r"(r1), "=r"(r2), "=r"(r3) : "r"(a))

#define MMA_F16R(d, a0, a1, a2, a3, b0, b1)                                \
    asm volatile(                                                          \
        "mma.sync.aligned.m16n8k16.row.col.f32.f16.f16.f32 "               \
        "{%0,%1,%2,%3}, {%4,%5,%6,%7}, {%8,%9}, {%0,%1,%2,%3};"            \
        : "+f"(d[0]), "+f"(d[1]), "+f"(d[2]), "+f"(d[3])                   \
        : "r"(a0), "r"(a1), "r"(a2), "r"(a3), "r"(b0), "r"(b1))

#define MMA_F16(d, a, b) MMA_F16R(d, (a)[0], (a)[1], (a)[2], (a)[3], (b)[0], (b)[1])

// ---------------------------------------------------------------------------
// Prepass A: pack inputs fp32 -> fp16 pairs along k.
// ---------------------------------------------------------------------------
__global__ void __launch_bounds__(256) prepack_x_kernel(
    const float* __restrict__ q, const float* __restrict__ ctx)
{
    const int z = blockIdx.z;
    const float* src = (z == 0) ? q : ctx;
    uint2* dst = (uint2*)((z == 0) ? g_Xqh : g_Xch);
    const int stride = gridDim.x * blockDim.x;
    const int count = MROWS * KP / 2;
    for (int i = blockIdx.x * blockDim.x + threadIdx.x; i < count; i += stride) {
        float4 v = ((const float4*)src)[i];
        dst[i] = make_uint2(f2h2(v.x, v.y), f2h2(v.z, v.w));
    }
}

// ---------------------------------------------------------------------------
// Prepass B: transpose+pack weights: W[k][n] fp32 -> Wt[n][kp] u32 (k-pairs).
// Tile 64k x 32n through smem; coalesced on both sides.
// ---------------------------------------------------------------------------
__global__ void __launch_bounds__(256) transpose_w_kernel(
    const float* __restrict__ Wq, const float* __restrict__ Wk,
    const float* __restrict__ Wv, const float* __restrict__ Wo)
{
    __shared__ float ws[64][33];
    const int z = blockIdx.z;
    const float* W = (z == 0) ? Wq : (z == 1) ? Wk : (z == 2) ? Wv : Wo;
    uint32_t* Wt = g_Wt[z];
    const int kb = blockIdx.x * 64;    // k block
    const int nb = blockIdx.y * 32;    // n block
    const int tid = threadIdx.x;

    #pragma unroll
    for (int i = 0; i < 8; i++) {
        int idx = tid + i * 256;       // 0..2047
        int r = idx >> 5;              // k row 0..63
        int c = idx & 31;              // n col 0..31
        ws[r][c] = W[(size_t)(kb + r) * EMBED + nb + c];
    }
    __syncthreads();
    #pragma unroll
    for (int i = 0; i < 4; i++) {
        int idx = tid + i * 256;       // 0..1023
        int n  = idx >> 5;             // 0..31
        int kp = idx & 31;             // 0..31
        Wt[(size_t)(nb + n) * KP + (kb >> 1) + kp] =
            f2h2(ws[2 * kp][n], ws[2 * kp + 1][n]);
    }
}

// ---------------------------------------------------------------------------
// fp16 GEMM + bias, 3-stage cp.async pipeline + ldmatrix fragments.
// CTA 128x128, BK=32, 256 threads (8 warps 2x4), warp tile 64x32.
// A smem [128][20] (row-major, k-pairs); B smem [128][20] ([n][kp]).
// ---------------------------------------------------------------------------
#define NSTG 3
#define PT   20                       // stage pitch (u32): 16 data + 4 pad
#define TSTG (128 * PT)               // 2560 u32 per tile-stage
#define GSMEM ((NSTG * 2 * TSTG) * 4) // 61440 B

__device__ __forceinline__ void gemm_h_body(
    const uint32_t* __restrict__ A, const uint32_t* __restrict__ Wt,
    const float* __restrict__ bias, void* __restrict__ Cout,
    int outHalf, float oscale, int bx, int by)
{
    extern __shared__ uint32_t gsm[];
    uint32_t* As = gsm;                 // [NSTG][128][PT]
    uint32_t* Bs = gsm + NSTG * TSTG;   // [NSTG][128][PT]
    const uint32_t sAs = smem_u32(As);
    const uint32_t sBs = smem_u32(Bs);

    const int tid  = threadIdx.x;
    const int lane = tid & 31;
    const int warp = tid >> 5;             // 0..7
    const int g    = lane >> 2;
    const int tg   = lane & 3;
    const int wr   = (warp >> 2) * 64;     // 0,64
    const int wc   = (warp & 3) * 32;      // 0,32,64,96
    const int rowBase = by * 128;
    const int colBase = bx * 128;
    const int KT = 32;                     // 1024 / 32

    // ldmatrix lane addressing
    const int arow  = wr + ((lane >> 3) & 1) * 8 + (lane & 7);  // + mt*16
    const int ahalf = ((lane >> 4) & 1) * 4;
    const int brow  = wc + ((lane >> 4) & 1) * 8 + (lane & 7);  // + ntp*16
    const int bhalf = ((lane >> 3) & 1) * 4;

    // cp.async chunk coords (2 chunks each for A and B per stage)
    const int c0 = 2 * tid, c1 = 2 * tid + 1;
    const int r0_ = c0 >> 2, q0_ = (c0 & 3) * 4;
    const int r1_ = c1 >> 2, q1_ = (c1 & 3) * 4;

    const uint32_t* A0 = A  + (size_t)(rowBase + r0_) * KP + q0_;
    const uint32_t* A1 = A  + (size_t)(rowBase + r1_) * KP + q1_;
    const uint32_t* B0 = Wt + (size_t)(colBase + r0_) * KP + q0_;
    const uint32_t* B1 = Wt + (size_t)(colBase + r1_) * KP + q1_;

    auto issue = [&](int stg, int kt) {
        uint32_t sa = sAs + (uint32_t)(stg * TSTG) * 4;
        uint32_t sb = sBs + (uint32_t)(stg * TSTG) * 4;
        cp16(sa + (r0_ * PT + q0_) * 4, A0 + kt * 16);
        cp16(sa + (r1_ * PT + q1_) * 4, A1 + kt * 16);
        cp16(sb + (r0_ * PT + q0_) * 4, B0 + kt * 16);
        cp16(sb + (r1_ * PT + q1_) * 4, B1 + kt * 16);
        CP_COMMIT();
    };

    float acc[4][4][4];
    #pragma unroll
    for (int mt = 0; mt < 4; mt++)
        #pragma unroll
        for (int nt = 0; nt < 4; nt++)
            #pragma unroll
            for (int e = 0; e < 4; e++) acc[mt][nt][e] = 0.f;

    issue(0, 0);
    issue(1, 1);

    for (int kt = 0; kt < KT; kt++) {
        const int stg = kt % NSTG;
        if (kt + 1 < KT) { CP_WAIT(1); } else { CP_WAIT(0); }
        __syncthreads();

        const uint32_t aBase = sAs + (uint32_t)(stg * TSTG) * 4;
        const uint32_t bBase = sBs + (uint32_t)(stg * TSTG) * 4;

        #pragma unroll
        for (int s = 0; s < 2; s++) {
            uint32_t a[4][4];
            #pragma unroll
            for (int mt = 0; mt < 4; mt++)
                LDSM4(a[mt][0], a[mt][1], a[mt][2], a[mt][3],
                      aBase + (uint32_t)(((arow + mt * 16) * PT) + 8 * s + ahalf) * 4);
            #pragma unroll
            for (int ntp = 0; ntp < 2; ntp++) {
                uint32_t b0, b1, b2, b3;
                LDSM4(b0, b1, b2, b3,
                      bBase + (uint32_t)(((brow + ntp * 16) * PT) + 8 * s + bhalf) * 4);
                #pragma unroll
                for (int mt = 0; mt < 4; mt++) {
                    MMA_F16R(acc[mt][2 * ntp],     a[mt][0], a[mt][1], a[mt][2], a[mt][3], b0, b1);
                    MMA_F16R(acc[mt][2 * ntp + 1], a[mt][0], a[mt][1], a[mt][2], a[mt][3], b2, b3);
                }
            }
        }
        if (kt + 2 < KT) issue((kt + 2) % NSTG, kt + 2);
    }

    if (outHalf) {
        uint32_t* C = (uint32_t*)Cout;
        #pragma unroll
        for (int mt = 0; mt < 4; mt++) {
            #pragma unroll
            for (int nt = 0; nt < 4; nt++) {
                int row  = rowBase + wr + mt * 16 + g;
                int col  = colBase + wc + nt * 8 + 2 * tg;
                int colp = col >> 1;
                float2 bv = *(const float2*)&bias[col];
                C[(size_t)row * KP + colp] =
                    f2h2((acc[mt][nt][0] + bv.x) * oscale,
                         (acc[mt][nt][1] + bv.y) * oscale);
                C[(size_t)(row + 8) * KP + colp] =
                    f2h2((acc[mt][nt][2] + bv.x) * oscale,
                         (acc[mt][nt][3] + bv.y) * oscale);
            }
        }
    } else {
        float* C = (float*)Cout;
        #pragma unroll
        for (int mt = 0; mt < 4; mt++) {
            #pragma unroll
            for (int nt = 0; nt < 4; nt++) {
                int row = rowBase + wr + mt * 16 + g;
                int col = colBase + wc + nt * 8 + 2 * tg;
                float2 bv = *(const float2*)&bias[col];
                float2 r0 = make_float2(acc[mt][nt][0] + bv.x, acc[mt][nt][1] + bv.y);
                float2 r1 = make_float2(acc[mt][nt][2] + bv.x, acc[mt][nt][3] + bv.y);
                *(float2*)&C[(size_t)row * EMBED + col]       = r0;
                *(float2*)&C[(size_t)(row + 8) * EMBED + col] = r1;
            }
        }
    }
}

__global__ void __launch_bounds__(256) gemm_qkv_kernel(
    const float* __restrict__ bq, const float* __restrict__ bk,
    const float* __restrict__ bv)
{
    const int z = blockIdx.z;
    if (z == 0)      gemm_h_body(g_Xqh, g_Wt[0], bq, g_Qh, 1, 0.125f, blockIdx.x, blockIdx.y);
    else if (z == 1) gemm_h_body(g_Xch, g_Wt[1], bk, g_Kh, 1, 1.0f,   blockIdx.x, blockIdx.y);
    else             gemm_h_body(g_Xch, g_Wt[2], bv, g_Vf, 0, 1.0f,   blockIdx.x, blockIdx.y);
}

__global__ void __launch_bounds__(256) gemm_o_kernel(
    const float* __restrict__ bo, float* __restrict__ out)
{
    gemm_h_body(g_Ah, g_Wt[3], bo, out, 0, 1.0f, blockIdx.x, blockIdx.y);
}

// ---------------------------------------------------------------------------
// Flash attention fp16, P in registers, K fragments via ldmatrix.
// q-tile 128, 4 warps x 32 rows; kv tiles of 64; K/V double-buffered.
// ---------------------------------------------------------------------------
#define PKH 36
#define PVH 72
#define PPH 36
#define FSM_TOTAL ((2 * 64 * PKH + 2 * 32 * PVH + 128 * PPH) * 4)

__global__ void __launch_bounds__(128) flash_h_kernel()
{
    extern __shared__ uint32_t sm[];
    uint32_t* Ks = sm;
    uint32_t* Vs = sm + 2 * 64 * PKH;
    uint32_t* Qstage = sm + 2 * 64 * PKH + 2 * 32 * PVH;

    const int b  = blockIdx.z;
    const int h  = blockIdx.y;
    const int q0 = blockIdx.x * 128;
    const int tid  = threadIdx.x;
    const int lane = tid & 31;
    const int warp = tid >> 5;
    const int g    = lane >> 2;
    const int tg   = lane & 3;
    const int mrow = warp * 32;

    // ldmatrix lane addressing for K b-fragments (Ks is [kv][dp] = n-major)
    const int krow  = ((lane >> 4) & 1) * 8 + (lane & 7);   // + ntp*16
    const int khalf = ((lane >> 3) & 1) * 4;

    const uint32_t* Qb = g_Qh + (size_t)b * QLEN * KP + h * 32;
    const uint32_t* Kb = g_Kh + (size_t)b * CLEN * KP + h * 32;
    const float*    Vb = g_Vf + (size_t)b * CLEN * EMBED + h * HDIM;

    const int kvr = tid >> 3;
    const int dq  = (tid & 7) * 4;
    uint4 kpf[4];
    auto ldgK = [&](int kt) {
        #pragma unroll
        for (int i = 0; i < 4; i++)
            kpf[i] = *(const uint4*)&Kb[(size_t)(kt * 64 + kvr + 16 * i) * KP + dq];
    };
    auto stsK = [&](uint32_t* dst) {
        #pragma unroll
        for (int i = 0; i < 4; i++)
            *(uint4*)&dst[(kvr + 16 * i) * PKH + dq] = kpf[i];
    };

    const int va_ = tid >> 4;
    const int dcol = (tid & 15) * 4;
    float4 vpa[4], vpb[4];
    auto ldgV = [&](int kt) {
        #pragma unroll
        for (int i = 0; i < 4; i++) {
            int kv2 = kt * 64 + 2 * (va_ + 8 * i);
            vpa[i] = *(const float4*)&Vb[(size_t)kv2 * EMBED + dcol];
            vpb[i] = *(const float4*)&Vb[(size_t)(kv2 + 1) * EMBED + dcol];
        }
    };
    auto stsV = [&](uint32_t* dst) {
        #pragma unroll
        for (int i = 0; i < 4; i++) {
            uint4 u = make_uint4(f2h2(vpa[i].x, vpb[i].x), f2h2(vpa[i].y, vpb[i].y),
                                 f2h2(vpa[i].z, vpb[i].z), f2h2(vpa[i].w, vpb[i].w));
            *(uint4*)&dst[(va_ + 8 * i) * PVH + dcol] = u;
        }
    };

    #pragma unroll
    for (int i = 0; i < 8; i++) {
        int idx = tid + i * 128;
        int r = idx >> 3;
        int q4 = (idx & 7) * 4;
        uint4 v = *(const uint4*)&Qb[(size_t)(q0 + r) * KP + q4];
        *(uint4*)&Qstage[r * PPH + q4] = v;
    }
    ldgK(0);
    __syncthreads();

    uint32_t qf[2][4][4];
    #pragma unroll
    for (int mt = 0; mt < 2; mt++) {
        int m = mrow + mt * 16 + g;
        #pragma unroll
        for (int s = 0; s < 4; s++) {
            qf[mt][s][0] = Qstage[m * PPH + 8 * s + tg];
            qf[mt][s][1] = Qstage[(m + 8) * PPH + 8 * s + tg];
            qf[mt][s][2] = Qstage[m * PPH + 8 * s + tg + 4];
            qf[mt][s][3] = Qstage[(m + 8) * PPH + 8 * s + tg + 4];
        }
    }
    stsK(Ks);
    ldgV(0);
    stsV(Vs);
    __syncthreads();

    float m_[4], l_[4];
    #pragma unroll
    for (int i = 0; i < 4; i++) { m_[i] = -INFINITY; l_[i] = 0.f; }
    float o[2][8][4];
    #pragma unroll
    for (int mt = 0; mt < 2; mt++)
        #pragma unroll
        for (int nt = 0; nt < 8; nt++)
            #pragma unroll
            for (int e = 0; e < 4; e++) o[mt][nt][e] = 0.f;

    const int NT = CLEN / 64;
    for (int kt = 0; kt < NT; kt++) {
        const int buf = kt & 1;
        uint32_t* Kcur = Ks + buf * 64 * PKH;
        uint32_t* Vcur = Vs + buf * 32 * PVH;
        uint32_t* Knxt = Ks + (buf ^ 1) * 64 * PKH;
        uint32_t* Vnxt = Vs + (buf ^ 1) * 32 * PVH;
        const uint32_t kBase = smem_u32(Kcur) + (uint32_t)(krow * PKH + khalf) * 4;

        if (kt + 1 < NT) ldgK(kt + 1);

        float sacc[2][8][4];
        #pragma unroll
        for (int mt = 0; mt < 2; mt++)
            #pragma unroll
            for (int nt = 0; nt < 8; nt++)
                #pragma unroll
                for (int e = 0; e < 4; e++) sacc[mt][nt][e] = 0.f;

        #pragma unroll
        for (int s = 0; s < 4; s++) {
            #pragma unroll
            for (int ntp = 0; ntp < 4; ntp++) {
                uint32_t b0, b1, b2, b3;
                LDSM4(b0, b1, b2, b3,
                      kBase + (uint32_t)(ntp * 16 * PKH + 8 * s) * 4);
                MMA_F16R(sacc[0][2 * ntp],     qf[0][s][0], qf[0][s][1], qf[0][s][2], qf[0][s][3], b0, b1);
                MMA_F16R(sacc[1][2 * ntp],     qf[1][s][0], qf[1][s][1], qf[1][s][2], qf[1][s][3], b0, b1);
                MMA_F16R(sacc[0][2 * ntp + 1], qf[0][s][0], qf[0][s][1], qf[0][s][2], qf[0][s][3], b2, b3);
                MMA_F16R(sacc[1][2 * ntp + 1], qf[1][s][0], qf[1][s][1], qf[1][s][2], qf[1][s][3], b2, b3);
            }
        }

        if (kt + 1 < NT) {
            stsK(Knxt);
            ldgV(kt + 1);
        }

        #pragma unroll
        for (int mt = 0; mt < 2; mt++) {
            float mx0 = -INFINITY, mx1 = -INFINITY;
            #pragma unroll
            for (int nt = 0; nt < 8; nt++) {
                mx0 = fmaxf(mx0, fmaxf(sacc[mt][nt][0], sacc[mt][nt][1]));
                mx1 = fmaxf(mx1, fmaxf(sacc[mt][nt][2], sacc[mt][nt][3]));
            }
            #pragma unroll
            for (int off = 1; off < 4; off <<= 1) {
                mx0 = fmaxf(mx0, __shfl_xor_sync(0xffffffffu, mx0, off));
                mx1 = fmaxf(mx1, __shfl_xor_sync(0xffffffffu, mx1, off));
            }
            float mn0 = fmaxf(m_[2 * mt],     mx0);
            float mn1 = fmaxf(m_[2 * mt + 1], mx1);
            float c0 = __expf(m_[2 * mt]     - mn0);
            float c1 = __expf(m_[2 * mt + 1] - mn1);

            float rs0 = 0.f, rs1 = 0.f;
            #pragma unroll
            for (int nt = 0; nt < 8; nt++) {
                sacc[mt][nt][0] = __expf(sacc[mt][nt][0] - mn0);
                sacc[mt][nt][1] = __expf(sacc[mt][nt][1] - mn0);
                sacc[mt][nt][2] = __expf(sacc[mt][nt][2] - mn1);
                sacc[mt][nt][3] = __expf(sacc[mt][nt][3] - mn1);
                rs0 += sacc[mt][nt][0] + sacc[mt][nt][1];
                rs1 += sacc[mt][nt][2] + sacc[mt][nt][3];
            }
            #pragma unroll
            for (int off = 1; off < 4; off <<= 1) {
                rs0 += __shfl_xor_sync(0xffffffffu, rs0, off);
                rs1 += __shfl_xor_sync(0xffffffffu, rs1, off);
            }
            l_[2 * mt]     = l_[2 * mt]     * c0 + rs0;
            l_[2 * mt + 1] = l_[2 * mt + 1] * c1 + rs1;
            m_[2 * mt]     = mn0;
            m_[2 * mt + 1] = mn1;
            #pragma unroll
            for (int nt = 0; nt < 8; nt++) {
                o[mt][nt][0] *= c0; o[mt][nt][1] *= c0;
                o[mt][nt][2] *= c1; o[mt][nt][3] *= c1;
            }
        }

        #pragma unroll
        for (int s = 0; s < 4; s++) {
            uint32_t af[2][4];
            #pragma unroll
            for (int mt = 0; mt < 2; mt++) {
                af[mt][0] = f2h2(sacc[mt][2 * s][0],     sacc[mt][2 * s][1]);
                af[mt][1] = f2h2(sacc[mt][2 * s][2],     sacc[mt][2 * s][3]);
                af[mt][2] = f2h2(sacc[mt][2 * s + 1][0], sacc[mt][2 * s + 1][1]);
                af[mt][3] = f2h2(sacc[mt][2 * s + 1][2], sacc[mt][2 * s + 1][3]);
            }
            #pragma unroll
            for (int nt = 0; nt < 8; nt++) {
                uint32_t bf[2];
                bf[0] = Vcur[(8 * s + tg) * PVH + nt * 8 + g];
                bf[1] = Vcur[(8 * s + tg + 4) * PVH + nt * 8 + g];
                MMA_F16(o[0][nt], af[0], bf);
                MMA_F16(o[1][nt], af[1], bf);
            }
        }

        if (kt + 1 < NT) stsV(Vnxt);
        __syncthreads();
    }

    uint32_t* Ab = g_Ah + (size_t)b * QLEN * KP + h * 32;
    #pragma unroll
    for (int mt = 0; mt < 2; mt++) {
        float i0 = 1.f / l_[2 * mt];
        float i1 = 1.f / l_[2 * mt + 1];
        int r0 = q0 + mrow + mt * 16 + g;
        #pragma unroll
        for (int nt = 0; nt < 8; nt++) {
            int colp = nt * 4 + tg;
            Ab[(size_t)r0 * KP + colp]       = f2h2(o[mt][nt][0] * i0, o[mt][nt][1] * i0);
            Ab[(size_t)(r0 + 8) * KP + colp] = f2h2(o[mt][nt][2] * i1, o[mt][nt][3] * i1);
        }
    }
}

// ---------------------------------------------------------------------------
extern "C" void kernel_launch(void* const* d_in, const int* in_sizes, int n_in,
                              void* d_out, int out_size)
{
    const float* query   = (const float*)d_in[0];
    const float* context = (const float*)d_in[1];
    const float* Wq = (const float*)d_in[2];
    const float* bq = (const float*)d_in[3];
    const float* Wk = (const float*)d_in[4];
    const float* bk = (const float*)d_in[5];
    const float* Wv = (const float*)d_in[6];
    const float* bv = (const float*)d_in[7];
    const float* Wo = (const float*)d_in[8];
    const float* bo = (const float*)d_in[9];
    float* out = (float*)d_out;

    prepack_x_kernel<<<dim3(256, 1, 2), 256>>>(query, context);
    transpose_w_kernel<<<dim3(EMBED / 64, EMBED / 32, 4), 256>>>(Wq, Wk, Wv, Wo);

    cudaFuncSetAttribute(gemm_qkv_kernel,
                         cudaFuncAttributeMaxDynamicSharedMemorySize, GSMEM);
    cudaFuncSetAttribute(gemm_o_kernel,
                         cudaFuncAttributeMaxDynamicSharedMemorySize, GSMEM);

    dim3 gQKV(EMBED / 128, MROWS / 128, 3);   // (8, 32, 3)
    gemm_qkv_kernel<<<gQKV, 256, GSMEM>>>(bq, bk, bv);

    cudaFuncSetAttribute(flash_h_kernel,
                         cudaFuncAttributeMaxDynamicSharedMemorySize, FSM_TOTAL);
    flash_h_kernel<<<dim3(QLEN / 128, NHEADS, BATCH), 128, FSM_TOTAL>>>();

    dim3 gGemm(EMBED / 128, MROWS / 128);     // (8, 32)
    gemm_o_kernel<<<gGemm, 256, GSMEM>>>(bo, out);
}

// round 11
// speedup vs baseline: 1.0566x; 1.0264x over previous
#include <cuda_runtime.h>
#include <math.h>
#include <stdint.h>

#define EMBED   1024
#define NHEADS  16
#define HDIM    64
#define BATCH   2
#define QLEN    2048
#define CLEN    2048
#define MROWS   (BATCH * QLEN)   // 4096
#define KP      (EMBED / 2)      // 512 u32 pairs per row

__device__ __align__(16) uint32_t g_Xqh[MROWS * KP];
__device__ __align__(16) uint32_t g_Xch[MROWS * KP];
__device__ __align__(16) uint32_t g_Wt[4][EMBED * KP];   // transposed: [n][kp]
__device__ __align__(16) uint32_t g_Qh[MROWS * KP];      // Q * (0.125*log2e) fp16
__device__ __align__(16) uint32_t g_Kh[MROWS * KP];
__device__ __align__(16) uint32_t g_Vh[MROWS * KP];      // V fp16 (same layout as K)
__device__ __align__(16) uint32_t g_Ah[MROWS * KP];

__device__ __forceinline__ uint32_t f2h2(float lo, float hi) {
    uint32_t r;
    asm("cvt.rn.f16x2.f32 %0, %1, %2;" : "=r"(r) : "f"(hi), "f"(lo));
    return r;
}
__device__ __forceinline__ float ex2(float x) {
    float y;
    asm("ex2.approx.ftz.f32 %0, %1;" : "=f"(y) : "f"(x));
    return y;
}
__device__ __forceinline__ uint32_t smem_u32(const void* p) {
    return (uint32_t)__cvta_generic_to_shared(p);
}
__device__ __forceinline__ void cp16(uint32_t saddr, const void* g) {
    asm volatile("cp.async.cg.shared.global [%0], [%1], 16;" :: "r"(saddr), "l"(g));
}
#define CP_COMMIT() asm volatile("cp.async.commit_group;" ::: "memory")
#define CP_WAIT(n)  asm volatile("cp.async.wait_group %0;" :: "n"(n) : "memory")

#define LDSM4(r0, r1, r2, r3, a)                                           \
    asm volatile("ldmatrix.sync.aligned.m8n8.x4.shared.b16 {%0,%1,%2,%3}, [%4];" \
        : "=r"(r0), "=r"(r1), "=r"(r2), "=r"(r3) : "r"(a))
#define LDSM4T(r0, r1, r2, r3, a)                                          \
    asm volatile("ldmatrix.sync.aligned.m8n8.x4.trans.shared.b16 {%0,%1,%2,%3}, [%4];" \
        : "=r"(r0), "=r"(r1), "=r"(r2), "=r"(r3) : "r"(a))

#define MMA_F16R(d, a0, a1, a2, a3, b0, b1)                                \
    asm volatile(                                                          \
        "mma.sync.aligned.m16n8k16.row.col.f32.f16.f16.f32 "               \
        "{%0,%1,%2,%3}, {%4,%5,%6,%7}, {%8,%9}, {%0,%1,%2,%3};"            \
        : "+f"(d[0]), "+f"(d[1]), "+f"(d[2]), "+f"(d[3])                   \
        : "r"(a0), "r"(a1), "r"(a2), "r"(a3), "r"(b0), "r"(b1))

// ---------------------------------------------------------------------------
// Prepass A: pack inputs fp32 -> fp16 pairs along k.
// ---------------------------------------------------------------------------
__global__ void __launch_bounds__(256) prepack_x_kernel(
    const float* __restrict__ q, const float* __restrict__ ctx)
{
    const int z = blockIdx.z;
    const float* src = (z == 0) ? q : ctx;
    uint2* dst = (uint2*)((z == 0) ? g_Xqh : g_Xch);
    const int stride = gridDim.x * blockDim.x;
    const int count = MROWS * KP / 2;
    for (int i = blockIdx.x * blockDim.x + threadIdx.x; i < count; i += stride) {
        float4 v = ((const float4*)src)[i];
        dst[i] = make_uint2(f2h2(v.x, v.y), f2h2(v.z, v.w));
    }
}

// ---------------------------------------------------------------------------
// Prepass B: transpose+pack weights: W[k][n] fp32 -> Wt[n][kp] u32 (k-pairs).
// ---------------------------------------------------------------------------
__global__ void __launch_bounds__(256) transpose_w_kernel(
    const float* __restrict__ Wq, const float* __restrict__ Wk,
    const float* __restrict__ Wv, const float* __restrict__ Wo)
{
    __shared__ float ws[64][33];
    const int z = blockIdx.z;
    const float* W = (z == 0) ? Wq : (z == 1) ? Wk : (z == 2) ? Wv : Wo;
    uint32_t* Wt = g_Wt[z];
    const int kb = blockIdx.x * 64;
    const int nb = blockIdx.y * 32;
    const int tid = threadIdx.x;

    #pragma unroll
    for (int i = 0; i < 8; i++) {
        int idx = tid + i * 256;
        int r = idx >> 5;
        int c = idx & 31;
        ws[r][c] = W[(size_t)(kb + r) * EMBED + nb + c];
    }
    __syncthreads();
    #pragma unroll
    for (int i = 0; i < 4; i++) {
        int idx = tid + i * 256;
        int n  = idx >> 5;
        int kp = idx & 31;
        Wt[(size_t)(nb + n) * KP + (kb >> 1) + kp] =
            f2h2(ws[2 * kp][n], ws[2 * kp + 1][n]);
    }
}

// ---------------------------------------------------------------------------
// fp16 GEMM + bias, 3-stage cp.async pipeline + ldmatrix (unchanged from R10).
// ---------------------------------------------------------------------------
#define NSTG 3
#define PT   20
#define TSTG (128 * PT)
#define GSMEM ((NSTG * 2 * TSTG) * 4)

__device__ __forceinline__ void gemm_h_body(
    const uint32_t* __restrict__ A, const uint32_t* __restrict__ Wt,
    const float* __restrict__ bias, void* __restrict__ Cout,
    int outHalf, float oscale, int bx, int by)
{
    extern __shared__ uint32_t gsm[];
    uint32_t* As = gsm;
    uint32_t* Bs = gsm + NSTG * TSTG;
    const uint32_t sAs = smem_u32(As);
    const uint32_t sBs = smem_u32(Bs);

    const int tid  = threadIdx.x;
    const int lane = tid & 31;
    const int warp = tid >> 5;
    const int g    = lane >> 2;
    const int tg   = lane & 3;
    const int wr   = (warp >> 2) * 64;
    const int wc   = (warp & 3) * 32;
    const int rowBase = by * 128;
    const int colBase = bx * 128;
    const int KT = 32;

    const int arow  = wr + ((lane >> 3) & 1) * 8 + (lane & 7);
    const int ahalf = ((lane >> 4) & 1) * 4;
    const int brow  = wc + ((lane >> 4) & 1) * 8 + (lane & 7);
    const int bhalf = ((lane >> 3) & 1) * 4;

    const int c0 = 2 * tid, c1 = 2 * tid + 1;
    const int r0_ = c0 >> 2, q0_ = (c0 & 3) * 4;
    const int r1_ = c1 >> 2, q1_ = (c1 & 3) * 4;

    const uint32_t* A0 = A  + (size_t)(rowBase + r0_) * KP + q0_;
    const uint32_t* A1 = A  + (size_t)(rowBase + r1_) * KP + q1_;
    const uint32_t* B0 = Wt + (size_t)(colBase + r0_) * KP + q0_;
    const uint32_t* B1 = Wt + (size_t)(colBase + r1_) * KP + q1_;

    auto issue = [&](int stg, int kt) {
        uint32_t sa = sAs + (uint32_t)(stg * TSTG) * 4;
        uint32_t sb = sBs + (uint32_t)(stg * TSTG) * 4;
        cp16(sa + (r0_ * PT + q0_) * 4, A0 + kt * 16);
        cp16(sa + (r1_ * PT + q1_) * 4, A1 + kt * 16);
        cp16(sb + (r0_ * PT + q0_) * 4, B0 + kt * 16);
        cp16(sb + (r1_ * PT + q1_) * 4, B1 + kt * 16);
        CP_COMMIT();
    };

    float acc[4][4][4];
    #pragma unroll
    for (int mt = 0; mt < 4; mt++)
        #pragma unroll
        for (int nt = 0; nt < 4; nt++)
            #pragma unroll
            for (int e = 0; e < 4; e++) acc[mt][nt][e] = 0.f;

    issue(0, 0);
    issue(1, 1);

    for (int kt = 0; kt < KT; kt++) {
        const int stg = kt % NSTG;
        if (kt + 1 < KT) { CP_WAIT(1); } else { CP_WAIT(0); }
        __syncthreads();

        const uint32_t aBase = sAs + (uint32_t)(stg * TSTG) * 4;
        const uint32_t bBase = sBs + (uint32_t)(stg * TSTG) * 4;

        #pragma unroll
        for (int s = 0; s < 2; s++) {
            uint32_t a[4][4];
            #pragma unroll
            for (int mt = 0; mt < 4; mt++)
                LDSM4(a[mt][0], a[mt][1], a[mt][2], a[mt][3],
                      aBase + (uint32_t)(((arow + mt * 16) * PT) + 8 * s + ahalf) * 4);
            #pragma unroll
            for (int ntp = 0; ntp < 2; ntp++) {
                uint32_t b0, b1, b2, b3;
                LDSM4(b0, b1, b2, b3,
                      bBase + (uint32_t)(((brow + ntp * 16) * PT) + 8 * s + bhalf) * 4);
                #pragma unroll
                for (int mt = 0; mt < 4; mt++) {
                    MMA_F16R(acc[mt][2 * ntp],     a[mt][0], a[mt][1], a[mt][2], a[mt][3], b0, b1);
                    MMA_F16R(acc[mt][2 * ntp + 1], a[mt][0], a[mt][1], a[mt][2], a[mt][3], b2, b3);
                }
            }
        }
        if (kt + 2 < KT) issue((kt + 2) % NSTG, kt + 2);
    }

    if (outHalf) {
        uint32_t* C = (uint32_t*)Cout;
        #pragma unroll
        for (int mt = 0; mt < 4; mt++) {
            #pragma unroll
            for (int nt = 0; nt < 4; nt++) {
                int row  = rowBase + wr + mt * 16 + g;
                int col  = colBase + wc + nt * 8 + 2 * tg;
                int colp = col >> 1;
                float2 bv = *(const float2*)&bias[col];
                C[(size_t)row * KP + colp] =
                    f2h2((acc[mt][nt][0] + bv.x) * oscale,
                         (acc[mt][nt][1] + bv.y) * oscale);
                C[(size_t)(row + 8) * KP + colp] =
                    f2h2((acc[mt][nt][2] + bv.x) * oscale,
                         (acc[mt][nt][3] + bv.y) * oscale);
            }
        }
    } else {
        float* C = (float*)Cout;
        #pragma unroll
        for (int mt = 0; mt < 4; mt++) {
            #pragma unroll
            for (int nt = 0; nt < 4; nt++) {
                int row = rowBase + wr + mt * 16 + g;
                int col = colBase + wc + nt * 8 + 2 * tg;
                float2 bv = *(const float2*)&bias[col];
                float2 r0 = make_float2(acc[mt][nt][0] + bv.x, acc[mt][nt][1] + bv.y);
                float2 r1 = make_float2(acc[mt][nt][2] + bv.x, acc[mt][nt][3] + bv.y);
                *(float2*)&C[(size_t)row * EMBED + col]       = r0;
                *(float2*)&C[(size_t)(row + 8) * EMBED + col] = r1;
            }
        }
    }
}

#define QSCALE (0.125f * 1.44269504f)   // fold 1/sqrt(64) and log2(e) into Q

__global__ void __launch_bounds__(256) gemm_qkv_kernel(
    const float* __restrict__ bq, const float* __restrict__ bk,
    const float* __restrict__ bv)
{
    const int z = blockIdx.z;
    if (z == 0)      gemm_h_body(g_Xqh, g_Wt[0], bq, g_Qh, 1, QSCALE, blockIdx.x, blockIdx.y);
    else if (z == 1) gemm_h_body(g_Xch, g_Wt[1], bk, g_Kh, 1, 1.0f,   blockIdx.x, blockIdx.y);
    else             gemm_h_body(g_Xch, g_Wt[2], bv, g_Vh, 1, 1.0f,   blockIdx.x, blockIdx.y);
}

__global__ void __launch_bounds__(256) gemm_o_kernel(
    const float* __restrict__ bo, float* __restrict__ out)
{
    gemm_h_body(g_Ah, g_Wt[3], bo, out, 0, 1.0f, blockIdx.x, blockIdx.y);
}

// ---------------------------------------------------------------------------
// Flash attention fp16: 256 threads (8 warps x 16 q-rows), q-tile 128,
// kv tiles 64, K/V fp16 double-buffered via cp.async, ldmatrix fragments
// (K non-trans, V trans), P in registers, softmax in exp2 domain.
// ---------------------------------------------------------------------------
#define PKH 36
#define PPH 36
// Ks[2][64][PKH] + Vs[2][64][PKH] + Qstage[128][PPH]
#define FSM_TOTAL ((4 * 64 * PKH + 128 * PPH) * 4)   // 55296 B

__global__ void __launch_bounds__(256, 2) flash_h_kernel()
{
    extern __shared__ uint32_t sm[];
    uint32_t* Ks = sm;                       // [2][64][PKH]
    uint32_t* Vs = sm + 2 * 64 * PKH;        // [2][64][PKH]
    uint32_t* Qstage = sm + 4 * 64 * PKH;    // [128][PPH]

    const int b  = blockIdx.z;
    const int h  = blockIdx.y;
    const int q0 = blockIdx.x * 128;
    const int tid  = threadIdx.x;
    const int lane = tid & 31;
    const int warp = tid >> 5;               // 0..7
    const int g    = lane >> 2;
    const int tg   = lane & 3;
    const int mrow = warp * 16;

    // K ldmatrix (non-trans): tiles (kv-low/high) x (d-low/high)
    const int krow  = ((lane >> 4) & 1) * 8 + (lane & 7);
    const int khalf = ((lane >> 3) & 1) * 4;
    // V ldmatrix (trans): tiles (kv-low/high) x (d-low/high)
    const int vk = ((lane >> 3) & 1) * 8 + (lane & 7);
    const int vd = ((lane >> 4) & 1) * 4;

    const uint32_t* Qb = g_Qh + (size_t)b * QLEN * KP + h * 32;
    const uint32_t* Kb = g_Kh + (size_t)b * CLEN * KP + h * 32;
    const uint32_t* Vb = g_Vh + (size_t)b * CLEN * KP + h * 32;

    // cp.async chunk coords: 512 chunks per tile, 2 per thread
    const int c0 = 2 * tid, c1 = 2 * tid + 1;
    const int cr0 = c0 >> 3, cc0 = (c0 & 7) * 4;
    const int cr1 = c1 >> 3, cc1 = (c1 & 7) * 4;
    const uint32_t sKs = smem_u32(Ks);
    const uint32_t sVs = smem_u32(Vs);

    auto issueKV = [&](int buf, int kt) {
        uint32_t ks = sKs + (uint32_t)(buf * 64 * PKH) * 4;
        uint32_t vs = sVs + (uint32_t)(buf * 64 * PKH) * 4;
        cp16(ks + (uint32_t)(cr0 * PKH + cc0) * 4, Kb + (size_t)(kt * 64 + cr0) * KP + cc0);
        cp16(ks + (uint32_t)(cr1 * PKH + cc1) * 4, Kb + (size_t)(kt * 64 + cr1) * KP + cc1);
        cp16(vs + (uint32_t)(cr0 * PKH + cc0) * 4, Vb + (size_t)(kt * 64 + cr0) * KP + cc0);
        cp16(vs + (uint32_t)(cr1 * PKH + cc1) * 4, Vb + (size_t)(kt * 64 + cr1) * KP + cc1);
        CP_COMMIT();
    };

    // Stage Q tile: 128 rows x 32 u32 (1024 uint4 chunks, 4 per thread)
    #pragma unroll
    for (int i = 0; i < 4; i++) {
        int idx = tid + i * 256;
        int r = idx >> 3;
        int c = (idx & 7) * 4;
        uint4 v = *(const uint4*)&Qb[(size_t)(q0 + r) * KP + c];
        *(uint4*)&Qstage[r * PPH + c] = v;
    }
    issueKV(0, 0);
    __syncthreads();

    // Q fragments -> registers
    uint32_t qf[4][4];
    #pragma unroll
    for (int s = 0; s < 4; s++) {
        qf[s][0] = Qstage[(mrow + g) * PPH + 8 * s + tg];
        qf[s][1] = Qstage[(mrow + g + 8) * PPH + 8 * s + tg];
        qf[s][2] = Qstage[(mrow + g) * PPH + 8 * s + tg + 4];
        qf[s][3] = Qstage[(mrow + g + 8) * PPH + 8 * s + tg + 4];
    }

    float m0 = -INFINITY, m1 = -INFINITY, l0 = 0.f, l1 = 0.f;
    float o[8][4];
    #pragma unroll
    for (int nt = 0; nt < 8; nt++)
        #pragma unroll
        for (int e = 0; e < 4; e++) o[nt][e] = 0.f;

    const int NT = CLEN / 64;
    for (int kt = 0; kt < NT; kt++) {
        const int buf = kt & 1;
        if (kt + 1 < NT) issueKV(buf ^ 1, kt + 1);
        if (kt + 1 < NT) { CP_WAIT(1); } else { CP_WAIT(0); }
        __syncthreads();

        const uint32_t kBase = sKs + (uint32_t)(buf * 64 * PKH + krow * PKH + khalf) * 4;
        const uint32_t vBase = sVs + (uint32_t)(buf * 64 * PKH + vk * PKH + vd) * 4;

        // ---- S = Q K^T (16 x 64) ----
        float sacc[8][4];
        #pragma unroll
        for (int nt = 0; nt < 8; nt++)
            #pragma unroll
            for (int e = 0; e < 4; e++) sacc[nt][e] = 0.f;

        #pragma unroll
        for (int s = 0; s < 4; s++) {
            #pragma unroll
            for (int ntp = 0; ntp < 4; ntp++) {
                uint32_t b0, b1, b2, b3;
                LDSM4(b0, b1, b2, b3, kBase + (uint32_t)(ntp * 16 * PKH + 8 * s) * 4);
                MMA_F16R(sacc[2 * ntp],     qf[s][0], qf[s][1], qf[s][2], qf[s][3], b0, b1);
                MMA_F16R(sacc[2 * ntp + 1], qf[s][0], qf[s][1], qf[s][2], qf[s][3], b2, b3);
            }
        }

        // ---- online softmax (exp2 domain; log2e folded into Q) ----
        {
            float mx0 = -INFINITY, mx1 = -INFINITY;
            #pragma unroll
            for (int nt = 0; nt < 8; nt++) {
                mx0 = fmaxf(mx0, fmaxf(sacc[nt][0], sacc[nt][1]));
                mx1 = fmaxf(mx1, fmaxf(sacc[nt][2], sacc[nt][3]));
            }
            #pragma unroll
            for (int off = 1; off < 4; off <<= 1) {
                mx0 = fmaxf(mx0, __shfl_xor_sync(0xffffffffu, mx0, off));
                mx1 = fmaxf(mx1, __shfl_xor_sync(0xffffffffu, mx1, off));
            }
            float mn0 = fmaxf(m0, mx0), mn1 = fmaxf(m1, mx1);
            float cc0_ = ex2(m0 - mn0), cc1_ = ex2(m1 - mn1);

            float rs0 = 0.f, rs1 = 0.f;
            #pragma unroll
            for (int nt = 0; nt < 8; nt++) {
                sacc[nt][0] = ex2(sacc[nt][0] - mn0);
                sacc[nt][1] = ex2(sacc[nt][1] - mn0);
                sacc[nt][2] = ex2(sacc[nt][2] - mn1);
                sacc[nt][3] = ex2(sacc[nt][3] - mn1);
                rs0 += sacc[nt][0] + sacc[nt][1];
                rs1 += sacc[nt][2] + sacc[nt][3];
            }
            #pragma unroll
            for (int off = 1; off < 4; off <<= 1) {
                rs0 += __shfl_xor_sync(0xffffffffu, rs0, off);
                rs1 += __shfl_xor_sync(0xffffffffu, rs1, off);
            }
            l0 = l0 * cc0_ + rs0;
            l1 = l1 * cc1_ + rs1;
            m0 = mn0; m1 = mn1;
            #pragma unroll
            for (int nt = 0; nt < 8; nt++) {
                o[nt][0] *= cc0_; o[nt][1] *= cc0_;
                o[nt][2] *= cc1_; o[nt][3] *= cc1_;
            }
        }

        // ---- O += P V : P packed from regs, V fragments via ldmatrix.trans ----
        #pragma unroll
        for (int s = 0; s < 4; s++) {
            uint32_t a0 = f2h2(sacc[2 * s][0],     sacc[2 * s][1]);
            uint32_t a1 = f2h2(sacc[2 * s][2],     sacc[2 * s][3]);
            uint32_t a2 = f2h2(sacc[2 * s + 1][0], sacc[2 * s + 1][1]);
            uint32_t a3 = f2h2(sacc[2 * s + 1][2], sacc[2 * s + 1][3]);
            #pragma unroll
            for (int np = 0; np < 4; np++) {
                uint32_t v0, v1, v2, v3;
                LDSM4T(v0, v1, v2, v3, vBase + (uint32_t)(s * 16 * PKH + np * 8) * 4);
                MMA_F16R(o[2 * np],     a0, a1, a2, a3, v0, v1);
                MMA_F16R(o[2 * np + 1], a0, a1, a2, a3, v2, v3);
            }
        }
        __syncthreads();
    }

    // normalize + write fp16 pairs to g_Ah
    uint32_t* Ab = g_Ah + (size_t)b * QLEN * KP + h * 32;
    float i0 = 1.f / l0, i1 = 1.f / l1;
    int r0 = q0 + mrow + g;
    #pragma unroll
    for (int nt = 0; nt < 8; nt++) {
        int colp = nt * 4 + tg;
        Ab[(size_t)r0 * KP + colp]       = f2h2(o[nt][0] * i0, o[nt][1] * i0);
        Ab[(size_t)(r0 + 8) * KP + colp] = f2h2(o[nt][2] * i1, o[nt][3] * i1);
    }
}

// ---------------------------------------------------------------------------
extern "C" void kernel_launch(void* const* d_in, const int* in_sizes, int n_in,
                              void* d_out, int out_size)
{
    const float* query   = (const float*)d_in[0];
    const float* context = (const float*)d_in[1];
    const float* Wq = (const float*)d_in[2];
    const float* bq = (const float*)d_in[3];
    const float* Wk = (const float*)d_in[4];
    const float* bk = (const float*)d_in[5];
    const float* Wv = (const float*)d_in[6];
    const float* bv = (const float*)d_in[7];
    const float* Wo = (const float*)d_in[8];
    const float* bo = (const float*)d_in[9];
    float* out = (float*)d_out;

    prepack_x_kernel<<<dim3(256, 1, 2), 256>>>(query, context);
    transpose_w_kernel<<<dim3(EMBED / 64, EMBED / 32, 4), 256>>>(Wq, Wk, Wv, Wo);

    cudaFuncSetAttribute(gemm_qkv_kernel,
                         cudaFuncAttributeMaxDynamicSharedMemorySize, GSMEM);
    cudaFuncSetAttribute(gemm_o_kernel,
                         cudaFuncAttributeMaxDynamicSharedMemorySize, GSMEM);

    dim3 gQKV(EMBED / 128, MROWS / 128, 3);   // (8, 32, 3)
    gemm_qkv_kernel<<<gQKV, 256, GSMEM>>>(bq, bk, bv);

    cudaFuncSetAttribute(flash_h_kernel,
                         cudaFuncAttributeMaxDynamicSharedMemorySize, FSM_TOTAL);
    flash_h_kernel<<<dim3(QLEN / 128, NHEADS, BATCH), 256, FSM_TOTAL>>>();

    dim3 gGemm(EMBED / 128, MROWS / 128);     // (8, 32)
    gemm_o_kernel<<<gGemm, 256, GSMEM>>>(bo, out);
}

// round 12
// speedup vs baseline: 1.0923x; 1.0338x over previous
#include <cuda_runtime.h>
#include <math.h>
#include <stdint.h>

#define EMBED   1024
#define NHEADS  16
#define HDIM    64
#define BATCH   2
#define QLEN    2048
#define CLEN    2048
#define MROWS   (BATCH * QLEN)   // 4096
#define KP      (EMBED / 2)      // 512 u32 pairs per row

__device__ __align__(16) uint32_t g_Xqh[MROWS * KP];
__device__ __align__(16) uint32_t g_Xch[MROWS * KP];
__device__ __align__(16) uint32_t g_Wt[4][EMBED * KP];   // transposed: [n][kp]
__device__ __align__(16) uint32_t g_Qh[MROWS * KP];      // Q * (0.125*log2e) fp16
__device__ __align__(16) uint32_t g_Kh[MROWS * KP];
__device__ __align__(16) uint32_t g_Vh[MROWS * KP];
__device__ __align__(16) uint32_t g_Ah[MROWS * KP];

__device__ __forceinline__ uint32_t f2h2(float lo, float hi) {
    uint32_t r;
    asm("cvt.rn.f16x2.f32 %0, %1, %2;" : "=r"(r) : "f"(hi), "f"(lo));
    return r;
}
__device__ __forceinline__ float ex2(float x) {
    float y;
    asm("ex2.approx.ftz.f32 %0, %1;" : "=f"(y) : "f"(x));
    return y;
}
__device__ __forceinline__ uint32_t smem_u32(const void* p) {
    return (uint32_t)__cvta_generic_to_shared(p);
}
__device__ __forceinline__ void cp16(uint32_t saddr, const void* g) {
    asm volatile("cp.async.cg.shared.global [%0], [%1], 16;" :: "r"(saddr), "l"(g));
}
#define CP_COMMIT() asm volatile("cp.async.commit_group;" ::: "memory")
#define CP_WAIT(n)  asm volatile("cp.async.wait_group %0;" :: "n"(n) : "memory")

#define LDSM4(r0, r1, r2, r3, a)                                           \
    asm volatile("ldmatrix.sync.aligned.m8n8.x4.shared.b16 {%0,%1,%2,%3}, [%4];" \
        : "=r"(r0), "=r"(r1), "=r"(r2), "=r"(r3) : "r"(a))
#define LDSM4T(r0, r1, r2, r3, a)                                          \
    asm volatile("ldmatrix.sync.aligned.m8n8.x4.trans.shared.b16 {%0,%1,%2,%3}, [%4];" \
        : "=r"(r0), "=r"(r1), "=r"(r2), "=r"(r3) : "r"(a))

#define MMA_F16R(d, a0, a1, a2, a3, b0, b1)                                \
    asm volatile(                                                          \
        "mma.sync.aligned.m16n8k16.row.col.f32.f16.f16.f32 "               \
        "{%0,%1,%2,%3}, {%4,%5,%6,%7}, {%8,%9}, {%0,%1,%2,%3};"            \
        : "+f"(d[0]), "+f"(d[1]), "+f"(d[2]), "+f"(d[3])                   \
        : "r"(a0), "r"(a1), "r"(a2), "r"(a3), "r"(b0), "r"(b1))

// ---------------------------------------------------------------------------
// Prepass (single launch): z=0,1 pack inputs; z=2..5 transpose+pack weights.
// ---------------------------------------------------------------------------
__global__ void __launch_bounds__(256) prepack_kernel(
    const float* __restrict__ q, const float* __restrict__ ctx,
    const float* __restrict__ Wq, const float* __restrict__ Wk,
    const float* __restrict__ Wv, const float* __restrict__ Wo)
{
    const int z = blockIdx.z;
    const int tid = threadIdx.x;

    if (z < 2) {
        const float* src = (z == 0) ? q : ctx;
        uint2* dst = (uint2*)((z == 0) ? g_Xqh : g_Xch);
        const int blk = blockIdx.y * gridDim.x + blockIdx.x;   // 0..511
        const int stride = gridDim.x * gridDim.y * 256;
        const int count = MROWS * KP / 2;
        for (int i = blk * 256 + tid; i < count; i += stride) {
            float4 v = ((const float4*)src)[i];
            dst[i] = make_uint2(f2h2(v.x, v.y), f2h2(v.z, v.w));
        }
    } else {
        __shared__ float ws[64][33];
        const float* W = (z == 2) ? Wq : (z == 3) ? Wk : (z == 4) ? Wv : Wo;
        uint32_t* Wt = g_Wt[z - 2];
        const int kb = blockIdx.x * 64;
        const int nb = blockIdx.y * 32;
        #pragma unroll
        for (int i = 0; i < 8; i++) {
            int idx = tid + i * 256;
            int r = idx >> 5;
            int c = idx & 31;
            ws[r][c] = W[(size_t)(kb + r) * EMBED + nb + c];
        }
        __syncthreads();
        #pragma unroll
        for (int i = 0; i < 4; i++) {
            int idx = tid + i * 256;
            int n  = idx >> 5;
            int kp = idx & 31;
            Wt[(size_t)(nb + n) * KP + (kb >> 1) + kp] =
                f2h2(ws[2 * kp][n], ws[2 * kp + 1][n]);
        }
    }
}

// ---------------------------------------------------------------------------
// fp16 GEMM + bias, 3-stage cp.async pipeline + ldmatrix (unchanged).
// ---------------------------------------------------------------------------
#define NSTG 3
#define PT   20
#define TSTG (128 * PT)
#define GSMEM ((NSTG * 2 * TSTG) * 4)

__device__ __forceinline__ void gemm_h_body(
    const uint32_t* __restrict__ A, const uint32_t* __restrict__ Wt,
    const float* __restrict__ bias, void* __restrict__ Cout,
    int outHalf, float oscale, int bx, int by)
{
    extern __shared__ uint32_t gsm[];
    uint32_t* As = gsm;
    uint32_t* Bs = gsm + NSTG * TSTG;
    const uint32_t sAs = smem_u32(As);
    const uint32_t sBs = smem_u32(Bs);

    const int tid  = threadIdx.x;
    const int lane = tid & 31;
    const int warp = tid >> 5;
    const int g    = lane >> 2;
    const int tg   = lane & 3;
    const int wr   = (warp >> 2) * 64;
    const int wc   = (warp & 3) * 32;
    const int rowBase = by * 128;
    const int colBase = bx * 128;
    const int KT = 32;

    const int arow  = wr + ((lane >> 3) & 1) * 8 + (lane & 7);
    const int ahalf = ((lane >> 4) & 1) * 4;
    const int brow  = wc + ((lane >> 4) & 1) * 8 + (lane & 7);
    const int bhalf = ((lane >> 3) & 1) * 4;

    const int c0 = 2 * tid, c1 = 2 * tid + 1;
    const int r0_ = c0 >> 2, q0_ = (c0 & 3) * 4;
    const int r1_ = c1 >> 2, q1_ = (c1 & 3) * 4;

    const uint32_t* A0 = A  + (size_t)(rowBase + r0_) * KP + q0_;
    const uint32_t* A1 = A  + (size_t)(rowBase + r1_) * KP + q1_;
    const uint32_t* B0 = Wt + (size_t)(colBase + r0_) * KP + q0_;
    const uint32_t* B1 = Wt + (size_t)(colBase + r1_) * KP + q1_;

    auto issue = [&](int stg, int kt) {
        uint32_t sa = sAs + (uint32_t)(stg * TSTG) * 4;
        uint32_t sb = sBs + (uint32_t)(stg * TSTG) * 4;
        cp16(sa + (r0_ * PT + q0_) * 4, A0 + kt * 16);
        cp16(sa + (r1_ * PT + q1_) * 4, A1 + kt * 16);
        cp16(sb + (r0_ * PT + q0_) * 4, B0 + kt * 16);
        cp16(sb + (r1_ * PT + q1_) * 4, B1 + kt * 16);
        CP_COMMIT();
    };

    float acc[4][4][4];
    #pragma unroll
    for (int mt = 0; mt < 4; mt++)
        #pragma unroll
        for (int nt = 0; nt < 4; nt++)
            #pragma unroll
            for (int e = 0; e < 4; e++) acc[mt][nt][e] = 0.f;

    issue(0, 0);
    issue(1, 1);

    for (int kt = 0; kt < KT; kt++) {
        const int stg = kt % NSTG;
        if (kt + 1 < KT) { CP_WAIT(1); } else { CP_WAIT(0); }
        __syncthreads();

        const uint32_t aBase = sAs + (uint32_t)(stg * TSTG) * 4;
        const uint32_t bBase = sBs + (uint32_t)(stg * TSTG) * 4;

        #pragma unroll
        for (int s = 0; s < 2; s++) {
            uint32_t a[4][4];
            #pragma unroll
            for (int mt = 0; mt < 4; mt++)
                LDSM4(a[mt][0], a[mt][1], a[mt][2], a[mt][3],
                      aBase + (uint32_t)(((arow + mt * 16) * PT) + 8 * s + ahalf) * 4);
            #pragma unroll
            for (int ntp = 0; ntp < 2; ntp++) {
                uint32_t b0, b1, b2, b3;
                LDSM4(b0, b1, b2, b3,
                      bBase + (uint32_t)(((brow + ntp * 16) * PT) + 8 * s + bhalf) * 4);
                #pragma unroll
                for (int mt = 0; mt < 4; mt++) {
                    MMA_F16R(acc[mt][2 * ntp],     a[mt][0], a[mt][1], a[mt][2], a[mt][3], b0, b1);
                    MMA_F16R(acc[mt][2 * ntp + 1], a[mt][0], a[mt][1], a[mt][2], a[mt][3], b2, b3);
                }
            }
        }
        if (kt + 2 < KT) issue((kt + 2) % NSTG, kt + 2);
    }

    if (outHalf) {
        uint32_t* C = (uint32_t*)Cout;
        #pragma unroll
        for (int mt = 0; mt < 4; mt++) {
            #pragma unroll
            for (int nt = 0; nt < 4; nt++) {
                int row  = rowBase + wr + mt * 16 + g;
                int col  = colBase + wc + nt * 8 + 2 * tg;
                int colp = col >> 1;
                float2 bv = *(const float2*)&bias[col];
                C[(size_t)row * KP + colp] =
                    f2h2((acc[mt][nt][0] + bv.x) * oscale,
                         (acc[mt][nt][1] + bv.y) * oscale);
                C[(size_t)(row + 8) * KP + colp] =
                    f2h2((acc[mt][nt][2] + bv.x) * oscale,
                         (acc[mt][nt][3] + bv.y) * oscale);
            }
        }
    } else {
        float* C = (float*)Cout;
        #pragma unroll
        for (int mt = 0; mt < 4; mt++) {
            #pragma unroll
            for (int nt = 0; nt < 4; nt++) {
                int row = rowBase + wr + mt * 16 + g;
                int col = colBase + wc + nt * 8 + 2 * tg;
                float2 bv = *(const float2*)&bias[col];
                float2 r0 = make_float2(acc[mt][nt][0] + bv.x, acc[mt][nt][1] + bv.y);
                float2 r1 = make_float2(acc[mt][nt][2] + bv.x, acc[mt][nt][3] + bv.y);
                *(float2*)&C[(size_t)row * EMBED + col]       = r0;
                *(float2*)&C[(size_t)(row + 8) * EMBED + col] = r1;
            }
        }
    }
}

#define QSCALE (0.125f * 1.44269504f)

__global__ void __launch_bounds__(256) gemm_qkv_kernel(
    const float* __restrict__ bq, const float* __restrict__ bk,
    const float* __restrict__ bv)
{
    const int z = blockIdx.z;
    if (z == 0)      gemm_h_body(g_Xqh, g_Wt[0], bq, g_Qh, 1, QSCALE, blockIdx.x, blockIdx.y);
    else if (z == 1) gemm_h_body(g_Xch, g_Wt[1], bk, g_Kh, 1, 1.0f,   blockIdx.x, blockIdx.y);
    else             gemm_h_body(g_Xch, g_Wt[2], bv, g_Vh, 1, 1.0f,   blockIdx.x, blockIdx.y);
}

__global__ void __launch_bounds__(256) gemm_o_kernel(
    const float* __restrict__ bo, float* __restrict__ out)
{
    gemm_h_body(g_Ah, g_Wt[3], bo, out, 0, 1.0f, blockIdx.x, blockIdx.y);
}

// ---------------------------------------------------------------------------
// Flash attention fp16: 256 threads (8 warps x 16 q-rows), q-tile 128,
// kv tiles 64. 3-stage cp.async KV ring -> ONE barrier per tile.
// Row sums via ones-MMA. P in registers. exp2-domain softmax.
// ---------------------------------------------------------------------------
#define FST  3
#define PKH 36
#define PPH 36
// Ks[3][64][PKH] + Vs[3][64][PKH] + Qstage[128][PPH]
#define FSM_TOTAL ((FST * 2 * 64 * PKH + 128 * PPH) * 4)   // 73728 B

__global__ void __launch_bounds__(256, 2) flash_h_kernel()
{
    extern __shared__ uint32_t sm[];
    uint32_t* Ks = sm;                           // [FST][64][PKH]
    uint32_t* Vs = sm + FST * 64 * PKH;          // [FST][64][PKH]
    uint32_t* Qstage = sm + 2 * FST * 64 * PKH;  // [128][PPH]

    const int b  = blockIdx.z;
    const int h  = blockIdx.y;
    const int q0 = blockIdx.x * 128;
    const int tid  = threadIdx.x;
    const int lane = tid & 31;
    const int warp = tid >> 5;
    const int g    = lane >> 2;
    const int tg   = lane & 3;
    const int mrow = warp * 16;

    const int krow  = ((lane >> 4) & 1) * 8 + (lane & 7);
    const int khalf = ((lane >> 3) & 1) * 4;
    const int vk = ((lane >> 3) & 1) * 8 + (lane & 7);
    const int vd = ((lane >> 4) & 1) * 4;

    const uint32_t* Qb = g_Qh + (size_t)b * QLEN * KP + h * 32;
    const uint32_t* Kb = g_Kh + (size_t)b * CLEN * KP + h * 32;
    const uint32_t* Vb = g_Vh + (size_t)b * CLEN * KP + h * 32;

    const int c0 = 2 * tid, c1 = 2 * tid + 1;
    const int cr0 = c0 >> 3, cc0 = (c0 & 7) * 4;
    const int cr1 = c1 >> 3, cc1 = (c1 & 7) * 4;
    const uint32_t sKs = smem_u32(Ks);
    const uint32_t sVs = smem_u32(Vs);

    auto issueKV = [&](int stg, int kt) {
        uint32_t ks = sKs + (uint32_t)(stg * 64 * PKH) * 4;
        uint32_t vs = sVs + (uint32_t)(stg * 64 * PKH) * 4;
        cp16(ks + (uint32_t)(cr0 * PKH + cc0) * 4, Kb + (size_t)(kt * 64 + cr0) * KP + cc0);
        cp16(ks + (uint32_t)(cr1 * PKH + cc1) * 4, Kb + (size_t)(kt * 64 + cr1) * KP + cc1);
        cp16(vs + (uint32_t)(cr0 * PKH + cc0) * 4, Vb + (size_t)(kt * 64 + cr0) * KP + cc0);
        cp16(vs + (uint32_t)(cr1 * PKH + cc1) * 4, Vb + (size_t)(kt * 64 + cr1) * KP + cc1);
        CP_COMMIT();
    };

    #pragma unroll
    for (int i = 0; i < 4; i++) {
        int idx = tid + i * 256;
        int r = idx >> 3;
        int c = (idx & 7) * 4;
        uint4 v = *(const uint4*)&Qb[(size_t)(q0 + r) * KP + c];
        *(uint4*)&Qstage[r * PPH + c] = v;
    }
    issueKV(0, 0);
    issueKV(1, 1);
    __syncthreads();

    uint32_t qf[4][4];
    #pragma unroll
    for (int s = 0; s < 4; s++) {
        qf[s][0] = Qstage[(mrow + g) * PPH + 8 * s + tg];
        qf[s][1] = Qstage[(mrow + g + 8) * PPH + 8 * s + tg];
        qf[s][2] = Qstage[(mrow + g) * PPH + 8 * s + tg + 4];
        qf[s][3] = Qstage[(mrow + g + 8) * PPH + 8 * s + tg + 4];
    }

    const uint32_t ONES = 0x3C003C00u;   // (1.0h, 1.0h)
    float m0 = -INFINITY, m1 = -INFINITY, l0 = 0.f, l1 = 0.f;
    float o[8][4];
    #pragma unroll
    for (int nt = 0; nt < 8; nt++)
        #pragma unroll
        for (int e = 0; e < 4; e++) o[nt][e] = 0.f;

    const int NT = CLEN / 64;
    for (int kt = 0; kt < NT; kt++) {
        const int stg = kt % FST;
        if (kt + 1 < NT) { CP_WAIT(1); } else { CP_WAIT(0); }
        __syncthreads();   // stage stg ready; all warps done with stage (kt-1)%FST
        if (kt + 2 < NT) issueKV((kt + 2) % FST, kt + 2);

        const uint32_t kBase = sKs + (uint32_t)(stg * 64 * PKH + krow * PKH + khalf) * 4;
        const uint32_t vBase = sVs + (uint32_t)(stg * 64 * PKH + vk * PKH + vd) * 4;

        // ---- S = Q K^T (16 x 64) ----
        float sacc[8][4];
        #pragma unroll
        for (int nt = 0; nt < 8; nt++)
            #pragma unroll
            for (int e = 0; e < 4; e++) sacc[nt][e] = 0.f;

        #pragma unroll
        for (int s = 0; s < 4; s++) {
            #pragma unroll
            for (int ntp = 0; ntp < 4; ntp++) {
                uint32_t b0, b1, b2, b3;
                LDSM4(b0, b1, b2, b3, kBase + (uint32_t)(ntp * 16 * PKH + 8 * s) * 4);
                MMA_F16R(sacc[2 * ntp],     qf[s][0], qf[s][1], qf[s][2], qf[s][3], b0, b1);
                MMA_F16R(sacc[2 * ntp + 1], qf[s][0], qf[s][1], qf[s][2], qf[s][3], b2, b3);
            }
        }

        // ---- softmax: max-reduce, exp2, pack P; row-sum via ones-MMA ----
        float mx0 = -INFINITY, mx1 = -INFINITY;
        #pragma unroll
        for (int nt = 0; nt < 8; nt++) {
            mx0 = fmaxf(mx0, fmaxf(sacc[nt][0], sacc[nt][1]));
            mx1 = fmaxf(mx1, fmaxf(sacc[nt][2], sacc[nt][3]));
        }
        #pragma unroll
        for (int off = 1; off < 4; off <<= 1) {
            mx0 = fmaxf(mx0, __shfl_xor_sync(0xffffffffu, mx0, off));
            mx1 = fmaxf(mx1, __shfl_xor_sync(0xffffffffu, mx1, off));
        }
        float mn0 = fmaxf(m0, mx0), mn1 = fmaxf(m1, mx1);
        float corr0 = ex2(m0 - mn0), corr1 = ex2(m1 - mn1);

        uint32_t pf[4][4];   // P fragments (fp16 pairs)
        #pragma unroll
        for (int s = 0; s < 4; s++) {
            float p00 = ex2(sacc[2 * s][0] - mn0);
            float p01 = ex2(sacc[2 * s][1] - mn0);
            float p10 = ex2(sacc[2 * s][2] - mn1);
            float p11 = ex2(sacc[2 * s][3] - mn1);
            float p20 = ex2(sacc[2 * s + 1][0] - mn0);
            float p21 = ex2(sacc[2 * s + 1][1] - mn0);
            float p30 = ex2(sacc[2 * s + 1][2] - mn1);
            float p31 = ex2(sacc[2 * s + 1][3] - mn1);
            pf[s][0] = f2h2(p00, p01);
            pf[s][1] = f2h2(p10, p11);
            pf[s][2] = f2h2(p20, p21);
            pf[s][3] = f2h2(p30, p31);
        }

        // row sums: P(16x64) x ones(64x8) -> lacc (all columns identical)
        float lacc[4] = {0.f, 0.f, 0.f, 0.f};
        #pragma unroll
        for (int s = 0; s < 4; s++)
            MMA_F16R(lacc, pf[s][0], pf[s][1], pf[s][2], pf[s][3], ONES, ONES);

        l0 = l0 * corr0 + lacc[0];
        l1 = l1 * corr1 + lacc[2];
        m0 = mn0; m1 = mn1;
        #pragma unroll
        for (int nt = 0; nt < 8; nt++) {
            o[nt][0] *= corr0; o[nt][1] *= corr0;
            o[nt][2] *= corr1; o[nt][3] *= corr1;
        }

        // ---- O += P V ----
        #pragma unroll
        for (int s = 0; s < 4; s++) {
            #pragma unroll
            for (int np = 0; np < 4; np++) {
                uint32_t v0, v1, v2, v3;
                LDSM4T(v0, v1, v2, v3, vBase + (uint32_t)(s * 16 * PKH + np * 8) * 4);
                MMA_F16R(o[2 * np],     pf[s][0], pf[s][1], pf[s][2], pf[s][3], v0, v1);
                MMA_F16R(o[2 * np + 1], pf[s][0], pf[s][1], pf[s][2], pf[s][3], v2, v3);
            }
        }
    }

    uint32_t* Ab = g_Ah + (size_t)b * QLEN * KP + h * 32;
    float i0 = 1.f / l0, i1 = 1.f / l1;
    int r0 = q0 + mrow + g;
    #pragma unroll
    for (int nt = 0; nt < 8; nt++) {
        int colp = nt * 4 + tg;
        Ab[(size_t)r0 * KP + colp]       = f2h2(o[nt][0] * i0, o[nt][1] * i0);
        Ab[(size_t)(r0 + 8) * KP + colp] = f2h2(o[nt][2] * i1, o[nt][3] * i1);
    }
}

// ---------------------------------------------------------------------------
extern "C" void kernel_launch(void* const* d_in, const int* in_sizes, int n_in,
                              void* d_out, int out_size)
{
    const float* query   = (const float*)d_in[0];
    const float* context = (const float*)d_in[1];
    const float* Wq = (const float*)d_in[2];
    const float* bq = (const float*)d_in[3];
    const float* Wk = (const float*)d_in[4];
    const float* bk = (const float*)d_in[5];
    const float* Wv = (const float*)d_in[6];
    const float* bv = (const float*)d_in[7];
    const float* Wo = (const float*)d_in[8];
    const float* bo = (const float*)d_in[9];
    float* out = (float*)d_out;

    prepack_kernel<<<dim3(EMBED / 64, EMBED / 32, 6), 256>>>(query, context, Wq, Wk, Wv, Wo);

    cudaFuncSetAttribute(gemm_qkv_kernel,
                         cudaFuncAttributeMaxDynamicSharedMemorySize, GSMEM);
    cudaFuncSetAttribute(gemm_o_kernel,
                         cudaFuncAttributeMaxDynamicSharedMemorySize, GSMEM);

    dim3 gQKV(EMBED / 128, MROWS / 128, 3);   // (8, 32, 3)
    gemm_qkv_kernel<<<gQKV, 256, GSMEM>>>(bq, bk, bv);

    cudaFuncSetAttribute(flash_h_kernel,
                         cudaFuncAttributeMaxDynamicSharedMemorySize, FSM_TOTAL);
    flash_h_kernel<<<dim3(QLEN / 128, NHEADS, BATCH), 256, FSM_TOTAL>>>();

    dim3 gGemm(EMBED / 128, MROWS / 128);     // (8, 32)
    gemm_o_kernel<<<gGemm, 256, GSMEM>>>(bo, out);
}